// round 1
// baseline (speedup 1.0000x reference)
#include <cuda_runtime.h>
#include <cuda_bf16.h>
#include <math.h>
#include <stdint.h>

// Problem constants
#define BB 2
#define SS 2048
#define DD 1024
#define HH 16
#define DKK 64
#define NROWS (BB*SS)          // 4096
#define OUT_ELEMS ((size_t)BB*SS*DD)            // 4,194,304
#define P_ELEMS   ((size_t)BB*HH*SS*SS)         // 134,217,728

// Scratch: qh | kh | vh | o | maskbias
#define QH_OFF   ((size_t)0)
#define KH_OFF   ((size_t)4194304)
#define VH_OFF   ((size_t)8388608)
#define OO_OFF   ((size_t)12582912)
#define MB_OFF   ((size_t)16777216)
__device__ float g_scratch[16777216 + 4096];

// ---------------------------------------------------------------------------
// Mask conversion: detect dtype (bool/u8, int32, float32) by byte pattern,
// then write additive bias (-1e30 for masked keys).
// ---------------------------------------------------------------------------
__global__ void mask_kernel(const unsigned char* __restrict__ mraw, float* __restrict__ mb)
{
    __shared__ int flag1, flag3;
    int tid = threadIdx.x;
    if (tid == 0) { flag1 = 0; flag3 = 0; }
    __syncthreads();
    const int n = NROWS; // 4096 elements; scan first 4096 bytes (valid for all dtypes)
    for (int i = tid; i < n; i += blockDim.x) {
        unsigned char by = mraw[i];
        if (((i & 3) == 1) && by) flag1 = 1;   // only bool/u8 has nonzero here
        if (((i & 3) == 3) && by) flag3 = 1;   // float32 1.0f has 0x3F here
    }
    __syncthreads();
    int mode = flag1 ? 0 : (flag3 ? 2 : 1);    // 0=u8, 1=int32, 2=float32
    for (int i = tid; i < n; i += blockDim.x) {
        bool masked;
        if (mode == 0)      masked = (mraw[i] != 0);
        else if (mode == 1) masked = (((const int*)mraw)[i] != 0);
        else                masked = (((const float*)mraw)[i] != 0.0f);
        mb[i] = masked ? -1e30f : 0.0f;
    }
}

// ---------------------------------------------------------------------------
// SGEMM: C[M,N] = A[M,K] @ B[K,N] + bias[N]
// 128x128 tile, BK=8, 256 threads, 8x8 per thread.
// headMode=1: scatter to [B,H,S,DK] layout. headMode=0: row-major [M,N].
// ---------------------------------------------------------------------------
#define BM 128
#define BN 128
#define BKD 8
#define TM 8
#define TN 8

__global__ void __launch_bounds__(256) sgemm_kernel(
    const float* __restrict__ A, const float* __restrict__ Bm,
    const float* __restrict__ bias, float* __restrict__ out,
    int M, int N, int K, int headMode)
{
    __shared__ float As[BKD][BM];
    __shared__ float Bs[BKD][BN];

    int tid = threadIdx.x;
    int bx = blockIdx.x;   // N tile
    int by = blockIdx.y;   // M tile
    int tx = tid % 16;
    int ty = tid / 16;

    const float* Ablk = A + (size_t)by * BM * K;
    const float* Bblk = Bm + (size_t)bx * BN;

    int aRow = tid >> 1;
    int aCol = (tid & 1) * 4;
    int bRow = tid >> 5;
    int bCol = (tid & 31) * 4;

    float acc[TM][TN];
    #pragma unroll
    for (int i = 0; i < TM; i++)
        #pragma unroll
        for (int j = 0; j < TN; j++) acc[i][j] = 0.0f;

    for (int k0 = 0; k0 < K; k0 += BKD) {
        float4 a4 = *(const float4*)(Ablk + (size_t)aRow * K + k0 + aCol);
        As[aCol + 0][aRow] = a4.x;
        As[aCol + 1][aRow] = a4.y;
        As[aCol + 2][aRow] = a4.z;
        As[aCol + 3][aRow] = a4.w;
        float4 b4 = *(const float4*)(Bblk + (size_t)(k0 + bRow) * N + bCol);
        *(float4*)(&Bs[bRow][bCol]) = b4;
        __syncthreads();

        #pragma unroll
        for (int kk = 0; kk < BKD; kk++) {
            float rM[TM], rN[TN];
            #pragma unroll
            for (int i = 0; i < TM; i++) rM[i] = As[kk][ty * TM + i];
            #pragma unroll
            for (int j = 0; j < TN; j++) rN[j] = Bs[kk][tx * TN + j];
            #pragma unroll
            for (int i = 0; i < TM; i++)
                #pragma unroll
                for (int j = 0; j < TN; j++)
                    acc[i][j] += rM[i] * rN[j];
        }
        __syncthreads();
    }

    #pragma unroll
    for (int i = 0; i < TM; i++) {
        int row = by * BM + ty * TM + i;
        #pragma unroll
        for (int j = 0; j < TN; j++) {
            int col = bx * BN + tx * TN + j;
            float v = acc[i][j] + bias[col];
            if (headMode) {
                int b  = row >> 11;        // /S (2048)
                int s  = row & (SS - 1);
                int h  = col >> 6;         // /DK
                int dk = col & (DKK - 1);
                out[((((size_t)b * HH + h) * SS + s) * DKK) + dk] = v;
            } else {
                out[(size_t)row * N + col] = v;
            }
        }
    }
}

// ---------------------------------------------------------------------------
// Attention: per (b,h,16 q-rows). Full 16x2048 score rows in SMEM.
//  Phase 1: S = Q K^T * 0.125 + maskbias   (chunks of 128 keys)
//  Phase 2: row softmax, multiply by attn_bias, write p_attn, keep p in SMEM
//  Phase 3: O = P V                          (chunks of 128 keys)
// ---------------------------------------------------------------------------
#define TQ 16
#define KC 128
#define KT_LD (KC + 1)

// smem floats: sQ 1024 | sMB 2048 | sKT 64*129 | sV 128*64 | sS 16*2048
#define SM_Q   0
#define SM_MB  (SM_Q  + TQ*DKK)
#define SM_KT  (SM_MB + SS)
#define SM_V   (SM_KT + DKK*KT_LD)
#define SM_S   (SM_V  + KC*DKK)
#define SM_TOTAL_FLOATS (SM_S + TQ*SS)
#define ATT_SMEM_BYTES (SM_TOTAL_FLOATS * 4)

__global__ void __launch_bounds__(256) attention_kernel(
    const float* __restrict__ qh, const float* __restrict__ kh,
    const float* __restrict__ vh, const float* __restrict__ attn_bias,
    const float* __restrict__ maskbias,
    float* __restrict__ p_out, float* __restrict__ o_out)
{
    extern __shared__ float sm[];
    float* sQ  = sm + SM_Q;
    float* sMB = sm + SM_MB;
    float* sKT = sm + SM_KT;
    float* sV  = sm + SM_V;
    float* sS  = sm + SM_S;

    int bh = blockIdx.y;               // b*H + h
    int b  = bh >> 4;
    int h  = bh & 15;
    int q0 = blockIdx.x * TQ;
    int tid = threadIdx.x;

    const float* qh_bh = qh + (size_t)bh * SS * DKK;
    const float* kh_bh = kh + (size_t)bh * SS * DKK;
    const float* vh_bh = vh + (size_t)bh * SS * DKK;

    // Load Q tile and mask bias row
    for (int i = tid; i < TQ * DKK; i += 256) sQ[i] = qh_bh[(size_t)q0 * DKK + i];
    for (int i = tid; i < SS; i += 256)       sMB[i] = maskbias[b * SS + i];
    __syncthreads();

    int c0 = tid & 31;       // 0..31
    int g  = tid >> 5;       // 0..7 -> rows {g, g+8}

    // ---------------- Phase 1: scores ----------------
    for (int kb = 0; kb < SS; kb += KC) {
        // load K chunk transposed: sKT[d][c]
        for (int i = tid; i < KC * (DKK / 4); i += 256) {
            int c  = i >> 4;            // 0..127
            int d4 = (i & 15) * 4;      // 0,4,..,60
            float4 kv = *(const float4*)(kh_bh + (size_t)(kb + c) * DKK + d4);
            sKT[(d4 + 0) * KT_LD + c] = kv.x;
            sKT[(d4 + 1) * KT_LD + c] = kv.y;
            sKT[(d4 + 2) * KT_LD + c] = kv.z;
            sKT[(d4 + 3) * KT_LD + c] = kv.w;
        }
        __syncthreads();

        float acc[2][4];
        #pragma unroll
        for (int r = 0; r < 2; r++)
            #pragma unroll
            for (int c = 0; c < 4; c++) acc[r][c] = 0.0f;

        #pragma unroll
        for (int d0 = 0; d0 < DKK; d0 += 8) {
            float qr[2][8];
            #pragma unroll
            for (int dd = 0; dd < 8; dd++) {
                qr[0][dd] = sQ[g * DKK + d0 + dd];
                qr[1][dd] = sQ[(g + 8) * DKK + d0 + dd];
            }
            #pragma unroll
            for (int dd = 0; dd < 8; dd++) {
                int d = d0 + dd;
                #pragma unroll
                for (int cc = 0; cc < 4; cc++) {
                    float kv = sKT[d * KT_LD + c0 + cc * 32];
                    acc[0][cc] += qr[0][dd] * kv;
                    acc[1][cc] += qr[1][dd] * kv;
                }
            }
        }

        #pragma unroll
        for (int rr = 0; rr < 2; rr++) {
            int r = g + rr * 8;
            #pragma unroll
            for (int cc = 0; cc < 4; cc++) {
                int j = kb + c0 + cc * 32;
                sS[r * SS + j] = acc[rr][cc] * 0.125f + sMB[j];
            }
        }
        __syncthreads();
    }

    // ---------------- Phase 2: softmax + bias ----------------
    {
        int warp = tid >> 5;
        int lane = tid & 31;
        for (int r = warp; r < TQ; r += 8) {
            float* srow = sS + r * SS;
            float m = -1e30f;
            for (int j = lane; j < SS; j += 32) m = fmaxf(m, srow[j]);
            #pragma unroll
            for (int o = 16; o > 0; o >>= 1) m = fmaxf(m, __shfl_xor_sync(0xffffffffu, m, o));
            float l = 0.0f;
            for (int j = lane; j < SS; j += 32) {
                float e = __expf(srow[j] - m);
                srow[j] = e;
                l += e;
            }
            #pragma unroll
            for (int o = 16; o > 0; o >>= 1) l += __shfl_xor_sync(0xffffffffu, l, o);
            float inv = 1.0f / l;
            const float* brow = attn_bias + ((size_t)bh * SS + (q0 + r)) * SS;
            float* prow = p_out ? (p_out + ((size_t)bh * SS + (q0 + r)) * SS) : nullptr;
            for (int j = lane; j < SS; j += 32) {
                float p = srow[j] * inv * brow[j];
                srow[j] = p;
                if (prow) prow[j] = p;
            }
        }
    }
    __syncthreads();

    // ---------------- Phase 3: O = P V ----------------
    float oacc[2][2] = {{0.0f, 0.0f}, {0.0f, 0.0f}};
    for (int kb = 0; kb < SS; kb += KC) {
        for (int i = tid; i < KC * (DKK / 4); i += 256) {
            *(float4*)(sV + i * 4) = *(const float4*)(vh_bh + (size_t)kb * DKK + i * 4);
        }
        __syncthreads();

        #pragma unroll 2
        for (int kk0 = 0; kk0 < KC; kk0 += 8) {
            float pr[2][8];
            #pragma unroll
            for (int t8 = 0; t8 < 8; t8++) {
                pr[0][t8] = sS[g * SS + kb + kk0 + t8];
                pr[1][t8] = sS[(g + 8) * SS + kb + kk0 + t8];
            }
            #pragma unroll
            for (int t8 = 0; t8 < 8; t8++) {
                int kv = kk0 + t8;
                float v0 = sV[kv * DKK + c0];
                float v1 = sV[kv * DKK + c0 + 32];
                oacc[0][0] += pr[0][t8] * v0;
                oacc[0][1] += pr[0][t8] * v1;
                oacc[1][0] += pr[1][t8] * v0;
                oacc[1][1] += pr[1][t8] * v1;
            }
        }
        __syncthreads();
    }

    #pragma unroll
    for (int rr = 0; rr < 2; rr++) {
        int q = q0 + g + rr * 8;
        #pragma unroll
        for (int cc = 0; cc < 2; cc++) {
            int c = c0 + cc * 32;
            o_out[((size_t)(b * SS + q)) * DD + h * DKK + c] = oacc[rr][cc];
        }
    }
}

// ---------------------------------------------------------------------------
// Launch
// ---------------------------------------------------------------------------
extern "C" void kernel_launch(void* const* d_in, const int* in_sizes, int n_in,
                              void* d_out, int out_size)
{
    const float* q    = (const float*)d_in[0];
    const float* k    = (const float*)d_in[1];
    const float* v    = (const float*)d_in[2];
    const unsigned char* mraw = (const unsigned char*)d_in[3];
    const float* bias = (const float*)d_in[4];
    const float* Wq   = (const float*)d_in[5];
    const float* bq   = (const float*)d_in[6];
    const float* Wk   = (const float*)d_in[7];
    const float* bk   = (const float*)d_in[8];
    const float* Wv   = (const float*)d_in[9];
    const float* bv   = (const float*)d_in[10];
    const float* Wo   = (const float*)d_in[11];
    const float* bo   = (const float*)d_in[12];

    float* out = (float*)d_out;
    float* p_out = nullptr;
    if ((size_t)out_size >= OUT_ELEMS + P_ELEMS) p_out = out + OUT_ELEMS;

    float* scratch = nullptr;
    cudaGetSymbolAddress((void**)&scratch, g_scratch);
    float* g_qh = scratch + QH_OFF;
    float* g_kh = scratch + KH_OFF;
    float* g_vh = scratch + VH_OFF;
    float* g_o  = scratch + OO_OFF;
    float* g_mb = scratch + MB_OFF;

    static bool attr_set = false;
    if (!attr_set) {
        cudaFuncSetAttribute(attention_kernel,
                             cudaFuncAttributeMaxDynamicSharedMemorySize,
                             ATT_SMEM_BYTES);
        attr_set = true;
    }

    mask_kernel<<<1, 1024>>>(mraw, g_mb);

    dim3 gproj(DD / BN, NROWS / BM);  // (8, 32)
    sgemm_kernel<<<gproj, 256>>>(q, Wq, bq, g_qh, NROWS, DD, DD, 1);
    sgemm_kernel<<<gproj, 256>>>(k, Wk, bk, g_kh, NROWS, DD, DD, 1);
    sgemm_kernel<<<gproj, 256>>>(v, Wv, bv, g_vh, NROWS, DD, DD, 1);

    dim3 gatt(SS / TQ, BB * HH);      // (128, 32)
    attention_kernel<<<gatt, 256, ATT_SMEM_BYTES>>>(g_qh, g_kh, g_vh, bias, g_mb,
                                                    p_out, g_o);

    sgemm_kernel<<<gproj, 256>>>(g_o, Wo, bo, out, NROWS, DD, DD, 0);
}

// round 2
// speedup vs baseline: 2.4430x; 2.4430x over previous
#include <cuda_runtime.h>
#include <cuda_bf16.h>
#include <math.h>
#include <stdint.h>

typedef unsigned int u32;

#define BB 2
#define SS 2048
#define DD 1024
#define HH 16
#define DKK 64
#define NROWS (BB*SS)                       // 4096
#define OUT_ELEMS ((size_t)BB*SS*DD)        // 4,194,304
#define P_ELEMS   ((size_t)BB*HH*SS*SS)     // 134,217,728

// ---------------------------------------------------------------------------
// Device scratch (allocation-free): bf16 hi/lo splits + small fp32 buffers
// ---------------------------------------------------------------------------
__device__ __nv_bfloat16 g_qh_hi[NROWS*DD];
__device__ __nv_bfloat16 g_qh_lo[NROWS*DD];
__device__ __nv_bfloat16 g_kh_hi[NROWS*DD];
__device__ __nv_bfloat16 g_kh_lo[NROWS*DD];
__device__ __nv_bfloat16 g_vh_hi[NROWS*DD];
__device__ __nv_bfloat16 g_vh_lo[NROWS*DD];
__device__ __nv_bfloat16 g_o_hi[NROWS*DD];
__device__ __nv_bfloat16 g_o_lo[NROWS*DD];
__device__ float g_mb[BB*SS];
__device__ float g_invl[BB*HH*SS];

// ---------------------------------------------------------------------------
// Helpers
// ---------------------------------------------------------------------------
__device__ __forceinline__ void mma16816(float* c, u32 a0, u32 a1, u32 a2, u32 a3,
                                         u32 b0, u32 b1)
{
    asm volatile(
        "mma.sync.aligned.m16n8k16.row.col.f32.bf16.bf16.f32 "
        "{%0,%1,%2,%3},{%4,%5,%6,%7},{%8,%9},{%0,%1,%2,%3};\n"
        : "+f"(c[0]), "+f"(c[1]), "+f"(c[2]), "+f"(c[3])
        : "r"(a0), "r"(a1), "r"(a2), "r"(a3), "r"(b0), "r"(b1));
}

__device__ __forceinline__ void f2bf_split(float v, __nv_bfloat16& h, __nv_bfloat16& l)
{
    h = __float2bfloat16_rn(v);
    l = __float2bfloat16_rn(v - __bfloat162float(h));
}

__device__ __forceinline__ u32 bf2_pack(__nv_bfloat16 a, __nv_bfloat16 b)
{
    __nv_bfloat162 t; t.x = a; t.y = b;
    return *reinterpret_cast<u32*>(&t);
}

__device__ __forceinline__ void split_pack2(float a, float b, u32& hp, u32& lp)
{
    __nv_bfloat16 ha, la, hb, lb;
    f2bf_split(a, ha, la);
    f2bf_split(b, hb, lb);
    hp = bf2_pack(ha, hb);
    lp = bf2_pack(la, lb);
}

// ---------------------------------------------------------------------------
// Mask conversion (dtype sniffing) -> additive bias (-1e30 for masked keys)
// ---------------------------------------------------------------------------
__global__ void mask_kernel(const unsigned char* __restrict__ mraw, float* __restrict__ mb)
{
    __shared__ int flag1, flag3;
    int tid = threadIdx.x;
    if (tid == 0) { flag1 = 0; flag3 = 0; }
    __syncthreads();
    const int n = NROWS;
    for (int i = tid; i < n; i += blockDim.x) {
        unsigned char by = mraw[i];
        if (((i & 3) == 1) && by) flag1 = 1;
        if (((i & 3) == 3) && by) flag3 = 1;
    }
    __syncthreads();
    int mode = flag1 ? 0 : (flag3 ? 2 : 1);
    for (int i = tid; i < n; i += blockDim.x) {
        bool masked;
        if (mode == 0)      masked = (mraw[i] != 0);
        else if (mode == 1) masked = (((const int*)mraw)[i] != 0);
        else                masked = (((const float*)mraw)[i] != 0.0f);
        mb[i] = masked ? -1e30f : 0.0f;
    }
}

// ---------------------------------------------------------------------------
// Tensor-core GEMM, bf16x3 split: C = A[M,K] @ B[K,N] + bias, x escale
// A source: fp32 (split on the fly) or pre-split bf16 hi/lo pair.
// headMode=1: store bf16 hi/lo pairs in head-major [B,H,S,DK]
// headMode=0: store fp32 row-major [M,N]
// CTA tile 128x128, K-tile 32, 8 warps (2x4), warp tile 64x32.
// ---------------------------------------------------------------------------
#define GLD 40   // smem row stride (bf16 units) for [row][32] tiles

__global__ void __launch_bounds__(256) tgemm_kernel(
    const float* __restrict__ Afp,
    const __nv_bfloat16* __restrict__ Ahi, const __nv_bfloat16* __restrict__ Alo,
    const float* __restrict__ Bfp, const float* __restrict__ bias,
    float* __restrict__ outF,
    __nv_bfloat16* __restrict__ outHi, __nv_bfloat16* __restrict__ outLo,
    int M, int N, int K, int headMode, float escale)
{
    __shared__ __nv_bfloat16 sAh[128*GLD], sAl[128*GLD];
    __shared__ __nv_bfloat16 sBh[128*GLD], sBl[128*GLD];

    int tid  = threadIdx.x;
    int wid  = tid >> 5;
    int lane = tid & 31;
    int g    = lane >> 2;
    int tg   = lane & 3;
    int m0 = blockIdx.y * 128;
    int n0 = blockIdx.x * 128;
    int wm = (wid & 1) * 64;
    int wn = (wid >> 1) * 32;

    float acc[4][4][4];
    #pragma unroll
    for (int mt = 0; mt < 4; mt++)
        #pragma unroll
        for (int nt = 0; nt < 4; nt++)
            #pragma unroll
            for (int i = 0; i < 4; i++) acc[mt][nt][i] = 0.0f;

    for (int k0 = 0; k0 < K; k0 += 32) {
        // ---- stage A (128 rows x 32 k) ----
        if (Afp) {
            #pragma unroll
            for (int i = 0; i < 4; i++) {
                int flat = i * 256 + tid;           // 0..1023
                int row  = flat >> 3;
                int kq   = (flat & 7) * 4;
                float4 a4 = *(const float4*)(Afp + (size_t)(m0 + row) * K + k0 + kq);
                __nv_bfloat16 h0, l0, h1, l1, h2, l2, h3, l3;
                f2bf_split(a4.x, h0, l0); f2bf_split(a4.y, h1, l1);
                f2bf_split(a4.z, h2, l2); f2bf_split(a4.w, h3, l3);
                *(u32*)&sAh[row*GLD + kq    ] = bf2_pack(h0, h1);
                *(u32*)&sAh[row*GLD + kq + 2] = bf2_pack(h2, h3);
                *(u32*)&sAl[row*GLD + kq    ] = bf2_pack(l0, l1);
                *(u32*)&sAl[row*GLD + kq + 2] = bf2_pack(l2, l3);
            }
        } else {
            #pragma unroll
            for (int i = 0; i < 8; i++) {
                int flat = i * 256 + tid;           // 0..2047
                int row  = flat >> 4;
                int kp   = (flat & 15) * 2;
                *(u32*)&sAh[row*GLD + kp] = *(const u32*)(Ahi + (size_t)(m0 + row) * K + k0 + kp);
                *(u32*)&sAl[row*GLD + kp] = *(const u32*)(Alo + (size_t)(m0 + row) * K + k0 + kp);
            }
        }
        // ---- stage B (32 k x 128 n) transposed to [n][k] ----
        #pragma unroll
        for (int i = 0; i < 16; i++) {
            int flat = i * 256 + tid;               // 0..4095
            int n  = flat & 127;
            int kk = flat >> 7;
            float v = Bfp[(size_t)(k0 + kk) * N + n0 + n];
            __nv_bfloat16 h, l;
            f2bf_split(v, h, l);
            sBh[n*GLD + kk] = h;
            sBl[n*GLD + kk] = l;
        }
        __syncthreads();

        #pragma unroll
        for (int ks = 0; ks < 32; ks += 16) {
            u32 af[4][2][4];
            #pragma unroll
            for (int mt = 0; mt < 4; mt++) {
                int r = wm + mt * 16 + g;
                af[mt][0][0] = *(u32*)&sAh[ r      *GLD + ks     + tg*2];
                af[mt][0][1] = *(u32*)&sAh[(r + 8) *GLD + ks     + tg*2];
                af[mt][0][2] = *(u32*)&sAh[ r      *GLD + ks + 8 + tg*2];
                af[mt][0][3] = *(u32*)&sAh[(r + 8) *GLD + ks + 8 + tg*2];
                af[mt][1][0] = *(u32*)&sAl[ r      *GLD + ks     + tg*2];
                af[mt][1][1] = *(u32*)&sAl[(r + 8) *GLD + ks     + tg*2];
                af[mt][1][2] = *(u32*)&sAl[ r      *GLD + ks + 8 + tg*2];
                af[mt][1][3] = *(u32*)&sAl[(r + 8) *GLD + ks + 8 + tg*2];
            }
            #pragma unroll
            for (int nt = 0; nt < 4; nt++) {
                int c = wn + nt * 8 + g;
                u32 b0h = *(u32*)&sBh[c*GLD + ks     + tg*2];
                u32 b1h = *(u32*)&sBh[c*GLD + ks + 8 + tg*2];
                u32 b0l = *(u32*)&sBl[c*GLD + ks     + tg*2];
                u32 b1l = *(u32*)&sBl[c*GLD + ks + 8 + tg*2];
                #pragma unroll
                for (int mt = 0; mt < 4; mt++) {
                    mma16816(acc[mt][nt], af[mt][0][0], af[mt][0][1], af[mt][0][2], af[mt][0][3], b0h, b1h);
                    mma16816(acc[mt][nt], af[mt][0][0], af[mt][0][1], af[mt][0][2], af[mt][0][3], b0l, b1l);
                    mma16816(acc[mt][nt], af[mt][1][0], af[mt][1][1], af[mt][1][2], af[mt][1][3], b0h, b1h);
                }
            }
        }
        __syncthreads();
    }

    // ---- epilogue ----
    #pragma unroll
    for (int mt = 0; mt < 4; mt++) {
        int r0 = m0 + wm + mt * 16 + g;
        int r1 = r0 + 8;
        #pragma unroll
        for (int nt = 0; nt < 4; nt++) {
            int c = n0 + wn + nt * 8 + tg * 2;
            float b0 = bias[c], b1 = bias[c + 1];
            float v00 = (acc[mt][nt][0] + b0) * escale;
            float v01 = (acc[mt][nt][1] + b1) * escale;
            float v10 = (acc[mt][nt][2] + b0) * escale;
            float v11 = (acc[mt][nt][3] + b1) * escale;
            if (headMode) {
                int h  = c >> 6;
                int dk = c & 63;
                int b_0 = r0 >> 11, s_0 = r0 & (SS - 1);
                int b_1 = r1 >> 11, s_1 = r1 & (SS - 1);
                size_t o0 = (((size_t)(b_0 * HH + h)) * SS + s_0) * DKK + dk;
                size_t o1 = (((size_t)(b_1 * HH + h)) * SS + s_1) * DKK + dk;
                __nv_bfloat16 h00, l00, h01, l01, h10, l10, h11, l11;
                f2bf_split(v00, h00, l00); f2bf_split(v01, h01, l01);
                f2bf_split(v10, h10, l10); f2bf_split(v11, h11, l11);
                *(u32*)&outHi[o0] = bf2_pack(h00, h01);
                *(u32*)&outLo[o0] = bf2_pack(l00, l01);
                *(u32*)&outHi[o1] = bf2_pack(h10, h11);
                *(u32*)&outLo[o1] = bf2_pack(l10, l11);
            } else {
                float2 w0; w0.x = v00; w0.y = v01;
                float2 w1; w1.x = v10; w1.y = v11;
                *(float2*)&outF[(size_t)r0 * N + c] = w0;
                *(float2*)&outF[(size_t)r1 * N + c] = w1;
            }
        }
    }
}

// ---------------------------------------------------------------------------
// Attention (single pass, tensor cores, bf16x3):
//   per chunk of 128 keys: S = Q K^T (+mask), e=exp(S), p^ = e*bias,
//   write p^ (unnormalized) to p_out, accumulate l = sum(e) and O += p^ V.
//   Epilogue: O /= l, store bf16 hi/lo; inv_l stored for p rescale kernel.
// CTA: 128 q-rows, 8 warps x 16 rows. grid (16 qtiles, 32 bh).
// ---------------------------------------------------------------------------
#define LDQ 72
#define LDV 136
#define SMB_BYTES (2048*4)
#define SQ_OFF  (SMB_BYTES)
#define ATT_SMEM_BYTES (SMB_BYTES + (9216*4 + 8704*2) * 2)

__global__ void __launch_bounds__(256) attn_kernel(
    const __nv_bfloat16* __restrict__ qh_hi, const __nv_bfloat16* __restrict__ qh_lo,
    const __nv_bfloat16* __restrict__ kh_hi, const __nv_bfloat16* __restrict__ kh_lo,
    const __nv_bfloat16* __restrict__ vh_hi, const __nv_bfloat16* __restrict__ vh_lo,
    const float* __restrict__ attn_bias, const float* __restrict__ maskbias,
    float* __restrict__ p_out, float* __restrict__ invl,
    __nv_bfloat16* __restrict__ o_hi, __nv_bfloat16* __restrict__ o_lo)
{
    extern __shared__ char smraw[];
    float* smb = (float*)smraw;                                   // 2048 f32
    __nv_bfloat16* sQh = (__nv_bfloat16*)(smraw + SQ_OFF);        // 128*72
    __nv_bfloat16* sQl = sQh + 9216;
    __nv_bfloat16* sKh = sQl + 9216;
    __nv_bfloat16* sKl = sKh + 9216;
    __nv_bfloat16* sVh = sKl + 9216;                              // 64*136
    __nv_bfloat16* sVl = sVh + 8704;

    int tid  = threadIdx.x;
    int wid  = tid >> 5;
    int lane = tid & 31;
    int g    = lane >> 2;
    int tg   = lane & 3;
    int bh = blockIdx.y;
    int b  = bh >> 4;
    int q0 = blockIdx.x * 128;
    int wq = wid * 16;

    // maskbias row for this batch
    #pragma unroll
    for (int i = tid; i < SS; i += 256) smb[i] = maskbias[b * SS + i];
    // Q tile
    for (int r = wid; r < 128; r += 8) {
        size_t go = ((size_t)bh * SS + q0 + r) * DKK + lane * 2;
        *(u32*)&sQh[r*LDQ + lane*2] = *(const u32*)(qh_hi + go);
        *(u32*)&sQl[r*LDQ + lane*2] = *(const u32*)(qh_lo + go);
    }
    __syncthreads();

    float lsum0 = 0.0f, lsum1 = 0.0f;
    float oacc[8][4];
    #pragma unroll
    for (int nt = 0; nt < 8; nt++)
        #pragma unroll
        for (int i = 0; i < 4; i++) oacc[nt][i] = 0.0f;

    int rr0 = q0 + wq + g;                 // this thread's first q row (in seq)
    const float* biasrow0 = attn_bias + ((size_t)bh * SS + rr0) * SS;
    const float* biasrow1 = biasrow0 + 8 * SS;
    float* prow0 = p_out ? p_out + ((size_t)bh * SS + rr0) * SS : nullptr;
    float* prow1 = prow0 ? prow0 + 8 * SS : nullptr;

    for (int kb = 0; kb < SS; kb += 128) {
        // ---- stage K chunk [128][64] and V chunk transposed [64][128] ----
        for (int r = wid; r < 128; r += 8) {
            size_t go = ((size_t)bh * SS + kb + r) * DKK + lane * 2;
            *(u32*)&sKh[r*LDQ + lane*2] = *(const u32*)(kh_hi + go);
            *(u32*)&sKl[r*LDQ + lane*2] = *(const u32*)(kh_lo + go);
            __nv_bfloat162 vh2 = *(const __nv_bfloat162*)(vh_hi + go);
            __nv_bfloat162 vl2 = *(const __nv_bfloat162*)(vh_lo + go);
            sVh[(2*lane    )*LDV + r] = vh2.x;
            sVh[(2*lane + 1)*LDV + r] = vh2.y;
            sVl[(2*lane    )*LDV + r] = vl2.x;
            sVl[(2*lane + 1)*LDV + r] = vl2.y;
        }
        __syncthreads();

        // ---- QK^T : scores sc[16][4] ----
        float sc[16][4];
        #pragma unroll
        for (int nt = 0; nt < 16; nt++)
            #pragma unroll
            for (int i = 0; i < 4; i++) sc[nt][i] = 0.0f;

        #pragma unroll
        for (int s = 0; s < 4; s++) {
            int r = wq + g;
            u32 ah0 = *(u32*)&sQh[ r      *LDQ + s*16     + tg*2];
            u32 ah1 = *(u32*)&sQh[(r + 8) *LDQ + s*16     + tg*2];
            u32 ah2 = *(u32*)&sQh[ r      *LDQ + s*16 + 8 + tg*2];
            u32 ah3 = *(u32*)&sQh[(r + 8) *LDQ + s*16 + 8 + tg*2];
            u32 al0 = *(u32*)&sQl[ r      *LDQ + s*16     + tg*2];
            u32 al1 = *(u32*)&sQl[(r + 8) *LDQ + s*16     + tg*2];
            u32 al2 = *(u32*)&sQl[ r      *LDQ + s*16 + 8 + tg*2];
            u32 al3 = *(u32*)&sQl[(r + 8) *LDQ + s*16 + 8 + tg*2];
            #pragma unroll
            for (int nt = 0; nt < 16; nt++) {
                int c = nt * 8 + g;
                u32 b0h = *(u32*)&sKh[c*LDQ + s*16     + tg*2];
                u32 b1h = *(u32*)&sKh[c*LDQ + s*16 + 8 + tg*2];
                u32 b0l = *(u32*)&sKl[c*LDQ + s*16     + tg*2];
                u32 b1l = *(u32*)&sKl[c*LDQ + s*16 + 8 + tg*2];
                mma16816(sc[nt], ah0, ah1, ah2, ah3, b0h, b1h);
                mma16816(sc[nt], ah0, ah1, ah2, ah3, b0l, b1l);
                mma16816(sc[nt], al0, al1, al2, al3, b0h, b1h);
            }
        }

        // ---- exp, bias multiply, p write, keep p^ in sc ----
        #pragma unroll
        for (int nt = 0; nt < 16; nt++) {
            int j = nt * 8 + tg * 2;
            float mb0 = smb[kb + j], mb1 = smb[kb + j + 1];
            float e0 = __expf(sc[nt][0] + mb0);
            float e1 = __expf(sc[nt][1] + mb1);
            float e2 = __expf(sc[nt][2] + mb0);
            float e3 = __expf(sc[nt][3] + mb1);
            lsum0 += e0 + e1;
            lsum1 += e2 + e3;
            float2 bi0 = *(const float2*)(biasrow0 + kb + j);
            float2 bi1 = *(const float2*)(biasrow1 + kb + j);
            float p0 = e0 * bi0.x, p1 = e1 * bi0.y;
            float p2 = e2 * bi1.x, p3 = e3 * bi1.y;
            if (prow0) {
                float2 w0; w0.x = p0; w0.y = p1;
                float2 w1; w1.x = p2; w1.y = p3;
                *(float2*)(prow0 + kb + j) = w0;
                *(float2*)(prow1 + kb + j) = w1;
            }
            sc[nt][0] = p0; sc[nt][1] = p1; sc[nt][2] = p2; sc[nt][3] = p3;
        }

        // ---- PV: O += p^ V ----
        #pragma unroll
        for (int s = 0; s < 8; s++) {
            u32 ah[4], al[4];
            split_pack2(sc[2*s    ][0], sc[2*s    ][1], ah[0], al[0]);
            split_pack2(sc[2*s    ][2], sc[2*s    ][3], ah[1], al[1]);
            split_pack2(sc[2*s + 1][0], sc[2*s + 1][1], ah[2], al[2]);
            split_pack2(sc[2*s + 1][2], sc[2*s + 1][3], ah[3], al[3]);
            #pragma unroll
            for (int nt = 0; nt < 8; nt++) {
                int c = nt * 8 + g;
                u32 b0h = *(u32*)&sVh[c*LDV + s*16     + tg*2];
                u32 b1h = *(u32*)&sVh[c*LDV + s*16 + 8 + tg*2];
                u32 b0l = *(u32*)&sVl[c*LDV + s*16     + tg*2];
                u32 b1l = *(u32*)&sVl[c*LDV + s*16 + 8 + tg*2];
                mma16816(oacc[nt], ah[0], ah[1], ah[2], ah[3], b0h, b1h);
                mma16816(oacc[nt], ah[0], ah[1], ah[2], ah[3], b0l, b1l);
                mma16816(oacc[nt], al[0], al[1], al[2], al[3], b0h, b1h);
            }
        }
        __syncthreads();
    }

    // ---- finalize: reduce l over quad, normalize O, store ----
    lsum0 += __shfl_xor_sync(0xffffffffu, lsum0, 1);
    lsum0 += __shfl_xor_sync(0xffffffffu, lsum0, 2);
    lsum1 += __shfl_xor_sync(0xffffffffu, lsum1, 1);
    lsum1 += __shfl_xor_sync(0xffffffffu, lsum1, 2);
    float il0 = 1.0f / lsum0;
    float il1 = 1.0f / lsum1;
    if (tg == 0) {
        invl[(size_t)bh * SS + rr0    ] = il0;
        invl[(size_t)bh * SS + rr0 + 8] = il1;
    }
    int grow0 = b * SS + rr0;
    int grow1 = grow0 + 8;
    int hcol  = (bh & 15) * DKK;
    #pragma unroll
    for (int nt = 0; nt < 8; nt++) {
        int c = hcol + nt * 8 + tg * 2;
        float v00 = oacc[nt][0] * il0, v01 = oacc[nt][1] * il0;
        float v10 = oacc[nt][2] * il1, v11 = oacc[nt][3] * il1;
        __nv_bfloat16 h00, l00, h01, l01, h10, l10, h11, l11;
        f2bf_split(v00, h00, l00); f2bf_split(v01, h01, l01);
        f2bf_split(v10, h10, l10); f2bf_split(v11, h11, l11);
        *(u32*)&o_hi[(size_t)grow0 * DD + c] = bf2_pack(h00, h01);
        *(u32*)&o_lo[(size_t)grow0 * DD + c] = bf2_pack(l00, l01);
        *(u32*)&o_hi[(size_t)grow1 * DD + c] = bf2_pack(h10, h11);
        *(u32*)&o_lo[(size_t)grow1 * DD + c] = bf2_pack(l10, l11);
    }
}

// ---------------------------------------------------------------------------
// p rescale: p *= inv_l[row]   (134M elements, float4)
// ---------------------------------------------------------------------------
__global__ void __launch_bounds__(256) pscale_kernel(float* __restrict__ p,
                                                     const float* __restrict__ invl)
{
    size_t idx = (size_t)blockIdx.x * 256 + threadIdx.x;   // float4 index
    float il = __ldg(invl + (idx >> 9));
    float4* p4 = (float4*)p;
    float4 v = p4[idx];
    v.x *= il; v.y *= il; v.z *= il; v.w *= il;
    p4[idx] = v;
}

// ---------------------------------------------------------------------------
// Launch
// ---------------------------------------------------------------------------
extern "C" void kernel_launch(void* const* d_in, const int* in_sizes, int n_in,
                              void* d_out, int out_size)
{
    const float* q    = (const float*)d_in[0];
    const float* k    = (const float*)d_in[1];
    const float* v    = (const float*)d_in[2];
    const unsigned char* mraw = (const unsigned char*)d_in[3];
    const float* bias = (const float*)d_in[4];
    const float* Wq   = (const float*)d_in[5];
    const float* bq   = (const float*)d_in[6];
    const float* Wk   = (const float*)d_in[7];
    const float* bk   = (const float*)d_in[8];
    const float* Wv   = (const float*)d_in[9];
    const float* bv   = (const float*)d_in[10];
    const float* Wo   = (const float*)d_in[11];
    const float* bo   = (const float*)d_in[12];

    float* out = (float*)d_out;
    float* p_out = ((size_t)out_size >= OUT_ELEMS + P_ELEMS) ? out + OUT_ELEMS : nullptr;

    __nv_bfloat16 *qh_hi, *qh_lo, *kh_hi, *kh_lo, *vh_hi, *vh_lo, *o_hi, *o_lo;
    float *mb, *invl;
    cudaGetSymbolAddress((void**)&qh_hi, g_qh_hi);
    cudaGetSymbolAddress((void**)&qh_lo, g_qh_lo);
    cudaGetSymbolAddress((void**)&kh_hi, g_kh_hi);
    cudaGetSymbolAddress((void**)&kh_lo, g_kh_lo);
    cudaGetSymbolAddress((void**)&vh_hi, g_vh_hi);
    cudaGetSymbolAddress((void**)&vh_lo, g_vh_lo);
    cudaGetSymbolAddress((void**)&o_hi,  g_o_hi);
    cudaGetSymbolAddress((void**)&o_lo,  g_o_lo);
    cudaGetSymbolAddress((void**)&mb,    g_mb);
    cudaGetSymbolAddress((void**)&invl,  g_invl);

    static bool attr_set = false;
    if (!attr_set) {
        cudaFuncSetAttribute(attn_kernel,
                             cudaFuncAttributeMaxDynamicSharedMemorySize,
                             ATT_SMEM_BYTES);
        attr_set = true;
    }

    mask_kernel<<<1, 1024>>>(mraw, mb);

    dim3 gp(DD / 128, NROWS / 128);   // (8, 32)
    tgemm_kernel<<<gp, 256>>>(q, nullptr, nullptr, Wq, bq, nullptr, qh_hi, qh_lo,
                              NROWS, DD, DD, 1, 0.125f);
    tgemm_kernel<<<gp, 256>>>(k, nullptr, nullptr, Wk, bk, nullptr, kh_hi, kh_lo,
                              NROWS, DD, DD, 1, 1.0f);
    tgemm_kernel<<<gp, 256>>>(v, nullptr, nullptr, Wv, bv, nullptr, vh_hi, vh_lo,
                              NROWS, DD, DD, 1, 1.0f);

    dim3 ga(SS / 128, BB * HH);       // (16, 32)
    attn_kernel<<<ga, 256, ATT_SMEM_BYTES>>>(qh_hi, qh_lo, kh_hi, kh_lo, vh_hi, vh_lo,
                                             bias, mb, p_out, invl, o_hi, o_lo);

    if (p_out) {
        pscale_kernel<<<(unsigned)(P_ELEMS / 4 / 256), 256>>>(p_out, invl);
    }

    tgemm_kernel<<<gp, 256>>>(nullptr, o_hi, o_lo, Wo, bo, out, nullptr, nullptr,
                              NROWS, DD, DD, 0, 1.0f);
}

// round 3
// speedup vs baseline: 4.2987x; 1.7596x over previous
#include <cuda_runtime.h>
#include <cuda_bf16.h>
#include <math.h>
#include <stdint.h>

typedef unsigned int u32;
typedef __nv_bfloat16 bf16;

#define BB 2
#define SS 2048
#define DD 1024
#define HH 16
#define DKK 64
#define NROWS (BB*SS)                       // 4096
#define OUT_ELEMS ((size_t)BB*SS*DD)
#define P_ELEMS   ((size_t)BB*HH*SS*SS)

// ---------------------------------------------------------------------------
// Device scratch (allocation-free)
// ---------------------------------------------------------------------------
__device__ __align__(16) bf16 g_aq_hi[NROWS*DD], g_aq_lo[NROWS*DD];
__device__ __align__(16) bf16 g_ak_hi[NROWS*DD], g_ak_lo[NROWS*DD];
__device__ __align__(16) bf16 g_av_hi[NROWS*DD], g_av_lo[NROWS*DD];
__device__ __align__(16) bf16 g_wT_hi[4][DD*DD], g_wT_lo[4][DD*DD];
__device__ __align__(16) bf16 g_qh_hi[NROWS*DD], g_qh_lo[NROWS*DD];
__device__ __align__(16) bf16 g_kh_hi[NROWS*DD], g_kh_lo[NROWS*DD];
__device__ __align__(16) bf16 g_vh_hi[NROWS*DD], g_vh_lo[NROWS*DD];
__device__ __align__(16) bf16 g_o_hi[NROWS*DD],  g_o_lo[NROWS*DD];
__device__ float g_mb[BB*SS];
__device__ float g_invl[BB*HH*SS];

// ---------------------------------------------------------------------------
// PTX helpers
// ---------------------------------------------------------------------------
__device__ __forceinline__ u32 cvta_s(const void* p) {
    return (u32)__cvta_generic_to_shared(p);
}
__device__ __forceinline__ void cp_async16(u32 dst, const void* src) {
    asm volatile("cp.async.cg.shared.global [%0], [%1], 16;\n" :: "r"(dst), "l"(src));
}
__device__ __forceinline__ void cp_commit() {
    asm volatile("cp.async.commit_group;\n" ::: "memory");
}
__device__ __forceinline__ void cp_wait0() {
    asm volatile("cp.async.wait_group 0;\n" ::: "memory");
}
__device__ __forceinline__ void ldsm_x4(u32* r, u32 addr) {
    asm volatile("ldmatrix.sync.aligned.m8n8.x4.shared.b16 {%0,%1,%2,%3}, [%4];\n"
        : "=r"(r[0]), "=r"(r[1]), "=r"(r[2]), "=r"(r[3]) : "r"(addr));
}
__device__ __forceinline__ void ldsm_x4_t(u32* r, u32 addr) {
    asm volatile("ldmatrix.sync.aligned.m8n8.x4.trans.shared.b16 {%0,%1,%2,%3}, [%4];\n"
        : "=r"(r[0]), "=r"(r[1]), "=r"(r[2]), "=r"(r[3]) : "r"(addr));
}
__device__ __forceinline__ void mma16816(float* c, u32 a0, u32 a1, u32 a2, u32 a3,
                                         u32 b0, u32 b1)
{
    asm volatile(
        "mma.sync.aligned.m16n8k16.row.col.f32.bf16.bf16.f32 "
        "{%0,%1,%2,%3},{%4,%5,%6,%7},{%8,%9},{%0,%1,%2,%3};\n"
        : "+f"(c[0]), "+f"(c[1]), "+f"(c[2]), "+f"(c[3])
        : "r"(a0), "r"(a1), "r"(a2), "r"(a3), "r"(b0), "r"(b1));
}
__device__ __forceinline__ void f2bf_split(float v, bf16& h, bf16& l) {
    h = __float2bfloat16_rn(v);
    l = __float2bfloat16_rn(v - __bfloat162float(h));
}
__device__ __forceinline__ u32 bf2_pack(bf16 a, bf16 b) {
    __nv_bfloat162 t; t.x = a; t.y = b;
    return *reinterpret_cast<u32*>(&t);
}
__device__ __forceinline__ void split_pack2(float a, float b, u32& hp, u32& lp) {
    bf16 ha, la, hb, lb;
    f2bf_split(a, ha, la);
    f2bf_split(b, hb, lb);
    hp = bf2_pack(ha, hb);
    lp = bf2_pack(la, lb);
}

// Stage a [128 rows x 64 bf16] tile into swizzled smem (128B rows, 16B chunk
// XOR swizzle: chunk' = chunk ^ (row & 7)). gstride_bytes = global row pitch.
__device__ __forceinline__ void stage128(u32 sbase, const bf16* g, u32 gstride_bytes, int tid) {
#pragma unroll
    for (int it = 0; it < 4; it++) {
        int idx = it * 256 + tid;
        int r = idx >> 3, c = idx & 7;
        cp_async16(sbase + (u32)(r * 128) + (u32)((c ^ (r & 7)) << 4),
                   (const char*)g + (size_t)r * gstride_bytes + (size_t)c * 16);
    }
}

// ---------------------------------------------------------------------------
// Mask conversion (dtype sniffing) -> additive bias (-1e30 for masked keys)
// ---------------------------------------------------------------------------
__global__ void mask_kernel(const unsigned char* __restrict__ mraw, float* __restrict__ mb)
{
    __shared__ int flag1, flag3;
    int tid = threadIdx.x;
    if (tid == 0) { flag1 = 0; flag3 = 0; }
    __syncthreads();
    const int n = NROWS;
    for (int i = tid; i < n; i += blockDim.x) {
        unsigned char by = mraw[i];
        if (((i & 3) == 1) && by) flag1 = 1;
        if (((i & 3) == 3) && by) flag3 = 1;
    }
    __syncthreads();
    int mode = flag1 ? 0 : (flag3 ? 2 : 1);
    for (int i = tid; i < n; i += blockDim.x) {
        bool masked;
        if (mode == 0)      masked = (mraw[i] != 0);
        else if (mode == 1) masked = (((const int*)mraw)[i] != 0);
        else                masked = (((const float*)mraw)[i] != 0.0f);
        mb[i] = masked ? -1e30f : 0.0f;
    }
}

// ---------------------------------------------------------------------------
// Pre-split kernels
// ---------------------------------------------------------------------------
__global__ void __launch_bounds__(256) split_kernel(
    const float4* __restrict__ x, uint2* __restrict__ hi, uint2* __restrict__ lo)
{
    int idx = blockIdx.x * 256 + threadIdx.x;
    float4 v = x[idx];
    bf16 h0, l0, h1, l1, h2, l2, h3, l3;
    f2bf_split(v.x, h0, l0); f2bf_split(v.y, h1, l1);
    f2bf_split(v.z, h2, l2); f2bf_split(v.w, h3, l3);
    uint2 ho; ho.x = bf2_pack(h0, h1); ho.y = bf2_pack(h2, h3);
    uint2 lu; lu.x = bf2_pack(l0, l1); lu.y = bf2_pack(l2, l3);
    hi[idx] = ho;
    lo[idx] = lu;
}

// Transpose+split 1024x1024 weight: out[n][k] = W[k][n]
__global__ void __launch_bounds__(256) splitT_kernel(
    const float* __restrict__ W, bf16* __restrict__ hiT, bf16* __restrict__ loT)
{
    __shared__ float t[32][33];
    int bx = blockIdx.x * 32, by = blockIdx.y * 32;
    int tx = threadIdx.x & 31, ty = threadIdx.x >> 5;   // ty 0..7
#pragma unroll
    for (int j = 0; j < 32; j += 8)
        t[ty + j][tx] = W[(size_t)(by + ty + j) * DD + bx + tx];
    __syncthreads();
#pragma unroll
    for (int j = 0; j < 32; j += 8) {
        float v = t[tx][ty + j];
        bf16 h, l;
        f2bf_split(v, h, l);
        size_t o = (size_t)(bx + ty + j) * DD + by + tx;
        hiT[o] = h;
        loT[o] = l;
    }
}

// ---------------------------------------------------------------------------
// Tensor-core GEMM (bf16x3): C = A[4096,1024] @ B^T  (B stored [N,K] hi/lo)
// 128x128 CTA tile, K-tile 64, cp.async double buffer, ldmatrix fragments.
// headMode=1: bf16 hi/lo head-major out; headMode=0: fp32 row-major out.
// smem: stage s at s*65536: Ah +0, Al +16384, Bh +32768, Bl +49152
// ---------------------------------------------------------------------------
#define TG_SMEM (2*65536)

__global__ void __launch_bounds__(256) tgemm_kernel(
    const bf16* __restrict__ Ahi, const bf16* __restrict__ Alo,
    const bf16* __restrict__ Bhi, const bf16* __restrict__ Blo,
    const float* __restrict__ bias,
    float* __restrict__ outF, bf16* __restrict__ outHi, bf16* __restrict__ outLo,
    int headMode, float escale)
{
    extern __shared__ char smc[];
    u32 sb = cvta_s(smc);

    int tid = threadIdx.x;
    int lane = tid & 31, wid = tid >> 5;
    int g = lane >> 2, tg = lane & 3;
    int i8 = lane & 7, sel = lane >> 3;
    int m0 = blockIdx.y * 128, n0 = blockIdx.x * 128;
    int wm = (wid & 1) * 64, wn = (wid >> 1) * 32;

    const size_t K = DD;
    const bf16* pAh = Ahi + (size_t)m0 * K;
    const bf16* pAl = Alo + (size_t)m0 * K;
    const bf16* pBh = Bhi + (size_t)n0 * K;
    const bf16* pBl = Blo + (size_t)n0 * K;

    float acc[4][4][4];
#pragma unroll
    for (int mt = 0; mt < 4; mt++)
#pragma unroll
        for (int nt = 0; nt < 4; nt++)
#pragma unroll
            for (int i = 0; i < 4; i++) acc[mt][nt][i] = 0.0f;

    // stage 0
    stage128(sb +     0, pAh, 2048, tid);
    stage128(sb + 16384, pAl, 2048, tid);
    stage128(sb + 32768, pBh, 2048, tid);
    stage128(sb + 49152, pBl, 2048, tid);
    cp_commit();

    for (int kt = 0; kt < 16; kt++) {
        cp_wait0();
        __syncthreads();
        u32 st = sb + (u32)((kt & 1) * 65536);
        if (kt < 15) {
            int k1 = (kt + 1) * 64;
            u32 sn = sb + (u32)(((kt + 1) & 1) * 65536);
            stage128(sn +     0, pAh + k1, 2048, tid);
            stage128(sn + 16384, pAl + k1, 2048, tid);
            stage128(sn + 32768, pBh + k1, 2048, tid);
            stage128(sn + 49152, pBl + k1, 2048, tid);
            cp_commit();
        }

#pragma unroll
        for (int ks4 = 0; ks4 < 4; ks4++) {
            int ks = ks4 * 16;
            u32 ah[4][4], al[4][4];
#pragma unroll
            for (int mt = 0; mt < 4; mt++) {
                int arow = wm + mt * 16 + i8 + ((sel & 1) << 3);
                u32 aoff = (u32)(arow * 128) + ((u32)((((ks >> 3) + (sel >> 1)) ^ i8)) << 4);
                ldsm_x4(ah[mt], st + aoff);
                ldsm_x4(al[mt], st + 16384 + aoff);
            }
#pragma unroll
            for (int ntp = 0; ntp < 2; ntp++) {
                int brow = wn + ntp * 16 + i8 + ((sel >> 1) << 3);
                u32 boff = (u32)(brow * 128) + ((u32)((((ks >> 3) + (sel & 1)) ^ i8)) << 4);
                u32 bh[4], bl[4];
                ldsm_x4(bh, st + 32768 + boff);
                ldsm_x4(bl, st + 49152 + boff);
#pragma unroll
                for (int mt = 0; mt < 4; mt++) {
                    mma16816(acc[mt][2*ntp],   ah[mt][0], ah[mt][1], ah[mt][2], ah[mt][3], bh[0], bh[1]);
                    mma16816(acc[mt][2*ntp],   ah[mt][0], ah[mt][1], ah[mt][2], ah[mt][3], bl[0], bl[1]);
                    mma16816(acc[mt][2*ntp],   al[mt][0], al[mt][1], al[mt][2], al[mt][3], bh[0], bh[1]);
                    mma16816(acc[mt][2*ntp+1], ah[mt][0], ah[mt][1], ah[mt][2], ah[mt][3], bh[2], bh[3]);
                    mma16816(acc[mt][2*ntp+1], ah[mt][0], ah[mt][1], ah[mt][2], ah[mt][3], bl[2], bl[3]);
                    mma16816(acc[mt][2*ntp+1], al[mt][0], al[mt][1], al[mt][2], al[mt][3], bh[2], bh[3]);
                }
            }
        }
    }

    // epilogue
#pragma unroll
    for (int mt = 0; mt < 4; mt++) {
        int r0 = m0 + wm + mt * 16 + g;
        int r1 = r0 + 8;
#pragma unroll
        for (int nt = 0; nt < 4; nt++) {
            int c = n0 + wn + nt * 8 + tg * 2;
            float b0 = bias[c], b1 = bias[c + 1];
            float v00 = (acc[mt][nt][0] + b0) * escale;
            float v01 = (acc[mt][nt][1] + b1) * escale;
            float v10 = (acc[mt][nt][2] + b0) * escale;
            float v11 = (acc[mt][nt][3] + b1) * escale;
            if (headMode) {
                int h  = c >> 6;
                int dk = c & 63;
                int b_0 = r0 >> 11, s_0 = r0 & (SS - 1);
                int b_1 = r1 >> 11, s_1 = r1 & (SS - 1);
                size_t o0 = (((size_t)(b_0 * HH + h)) * SS + s_0) * DKK + dk;
                size_t o1 = (((size_t)(b_1 * HH + h)) * SS + s_1) * DKK + dk;
                bf16 h00, l00, h01, l01, h10, l10, h11, l11;
                f2bf_split(v00, h00, l00); f2bf_split(v01, h01, l01);
                f2bf_split(v10, h10, l10); f2bf_split(v11, h11, l11);
                *(u32*)&outHi[o0] = bf2_pack(h00, h01);
                *(u32*)&outLo[o0] = bf2_pack(l00, l01);
                *(u32*)&outHi[o1] = bf2_pack(h10, h11);
                *(u32*)&outLo[o1] = bf2_pack(l10, l11);
            } else {
                float2 w0; w0.x = v00; w0.y = v01;
                float2 w1; w1.x = v10; w1.y = v11;
                *(float2*)&outF[(size_t)r0 * DD + c] = w0;
                *(float2*)&outF[(size_t)r1 * DD + c] = w1;
            }
        }
    }
}

// ---------------------------------------------------------------------------
// Attention (single pass, bf16x3, cp.async double-buffered K/V, ldmatrix)
// smem bytes: mb 0..8192 | Qh 8192 | Ql 24576 | stage s at 40960+s*65536:
//   Kh +0, Kl +16384, Vh +32768, Vl +49152
// ---------------------------------------------------------------------------
#define ATT_SMEM (8192 + 32768 + 2*65536)   // 172032

__global__ void __launch_bounds__(256) attn_kernel(
    const bf16* __restrict__ qh_hi, const bf16* __restrict__ qh_lo,
    const bf16* __restrict__ kh_hi, const bf16* __restrict__ kh_lo,
    const bf16* __restrict__ vh_hi, const bf16* __restrict__ vh_lo,
    const float* __restrict__ attn_bias, const float* __restrict__ maskbias,
    float* __restrict__ p_out, float* __restrict__ invl,
    bf16* __restrict__ o_hi, bf16* __restrict__ o_lo)
{
    extern __shared__ char smc[];
    u32 sb = cvta_s(smc);
    float* smb = (float*)smc;
    u32 sQh = sb + 8192;
    u32 sQl = sb + 24576;

    int tid = threadIdx.x;
    int lane = tid & 31, wid = tid >> 5;
    int g = lane >> 2, tg = lane & 3;
    int i8 = lane & 7, sel = lane >> 3;
    int bh = blockIdx.y;
    int b  = bh >> 4;
    int q0 = blockIdx.x * 128;
    int wq = wid * 16;

    const bf16* kb_h = kh_hi + (size_t)bh * SS * DKK;
    const bf16* kb_l = kh_lo + (size_t)bh * SS * DKK;
    const bf16* vb_h = vh_hi + (size_t)bh * SS * DKK;
    const bf16* vb_l = vh_lo + (size_t)bh * SS * DKK;

    // issue Q + stage0
    stage128(sQh, qh_hi + ((size_t)bh * SS + q0) * DKK, 128, tid);
    stage128(sQl, qh_lo + ((size_t)bh * SS + q0) * DKK, 128, tid);
    {
        u32 s0 = sb + 40960;
        stage128(s0 +     0, kb_h, 128, tid);
        stage128(s0 + 16384, kb_l, 128, tid);
        stage128(s0 + 32768, vb_h, 128, tid);
        stage128(s0 + 49152, vb_l, 128, tid);
    }
    cp_commit();

    for (int i = tid; i < SS; i += 256) smb[i] = maskbias[b * SS + i];

    float lsum0 = 0.0f, lsum1 = 0.0f;
    float oacc[8][4];
#pragma unroll
    for (int nt = 0; nt < 8; nt++)
#pragma unroll
        for (int i = 0; i < 4; i++) oacc[nt][i] = 0.0f;

    int rr0 = q0 + wq + g;
    const float* biasrow0 = attn_bias + ((size_t)bh * SS + rr0) * SS;
    const float* biasrow1 = biasrow0 + 8 * SS;
    float* prow0 = p_out ? p_out + ((size_t)bh * SS + rr0) * SS : nullptr;
    float* prow1 = prow0 ? prow0 + 8 * SS : nullptr;

    for (int kt = 0; kt < 16; kt++) {
        cp_wait0();
        __syncthreads();
        u32 st = sb + 40960 + (u32)((kt & 1) * 65536);
        if (kt < 15) {
            int kb1 = (kt + 1) * 128;
            u32 sn = sb + 40960 + (u32)(((kt + 1) & 1) * 65536);
            stage128(sn +     0, kb_h + (size_t)kb1 * DKK, 128, tid);
            stage128(sn + 16384, kb_l + (size_t)kb1 * DKK, 128, tid);
            stage128(sn + 32768, vb_h + (size_t)kb1 * DKK, 128, tid);
            stage128(sn + 49152, vb_l + (size_t)kb1 * DKK, 128, tid);
            cp_commit();
        }
        int kb = kt * 128;

        // ---- QK^T ----
        float sc[16][4];
#pragma unroll
        for (int nt = 0; nt < 16; nt++)
#pragma unroll
            for (int i = 0; i < 4; i++) sc[nt][i] = 0.0f;

#pragma unroll
        for (int ks4 = 0; ks4 < 4; ks4++) {
            int ks = ks4 * 16;
            int arow = wq + i8 + ((sel & 1) << 3);
            u32 aoff = (u32)(arow * 128) + ((u32)((((ks >> 3) + (sel >> 1)) ^ i8)) << 4);
            u32 qh[4], ql[4];
            ldsm_x4(qh, sQh + aoff);
            ldsm_x4(ql, sQl + aoff);
#pragma unroll
            for (int ntp = 0; ntp < 8; ntp++) {
                int brow = ntp * 16 + i8 + ((sel >> 1) << 3);
                u32 boff = (u32)(brow * 128) + ((u32)((((ks >> 3) + (sel & 1)) ^ i8)) << 4);
                u32 bhr[4], blr[4];
                ldsm_x4(bhr, st + boff);
                ldsm_x4(blr, st + 16384 + boff);
                mma16816(sc[2*ntp],   qh[0], qh[1], qh[2], qh[3], bhr[0], bhr[1]);
                mma16816(sc[2*ntp],   qh[0], qh[1], qh[2], qh[3], blr[0], blr[1]);
                mma16816(sc[2*ntp],   ql[0], ql[1], ql[2], ql[3], bhr[0], bhr[1]);
                mma16816(sc[2*ntp+1], qh[0], qh[1], qh[2], qh[3], bhr[2], bhr[3]);
                mma16816(sc[2*ntp+1], qh[0], qh[1], qh[2], qh[3], blr[2], blr[3]);
                mma16816(sc[2*ntp+1], ql[0], ql[1], ql[2], ql[3], bhr[2], bhr[3]);
            }
        }

        // ---- exp, bias multiply, p write, keep p^ in sc ----
#pragma unroll
        for (int nt = 0; nt < 16; nt++) {
            int j = nt * 8 + tg * 2;
            float mb0 = smb[kb + j], mb1 = smb[kb + j + 1];
            float e0 = __expf(sc[nt][0] + mb0);
            float e1 = __expf(sc[nt][1] + mb1);
            float e2 = __expf(sc[nt][2] + mb0);
            float e3 = __expf(sc[nt][3] + mb1);
            lsum0 += e0 + e1;
            lsum1 += e2 + e3;
            float2 bi0 = *(const float2*)(biasrow0 + kb + j);
            float2 bi1 = *(const float2*)(biasrow1 + kb + j);
            float p0 = e0 * bi0.x, p1 = e1 * bi0.y;
            float p2 = e2 * bi1.x, p3 = e3 * bi1.y;
            if (prow0) {
                float2 w0; w0.x = p0; w0.y = p1;
                float2 w1; w1.x = p2; w1.y = p3;
                *(float2*)(prow0 + kb + j) = w0;
                *(float2*)(prow1 + kb + j) = w1;
            }
            sc[nt][0] = p0; sc[nt][1] = p1; sc[nt][2] = p2; sc[nt][3] = p3;
        }

        // ---- PV: O += p^ V  (V fragments via ldmatrix.trans) ----
#pragma unroll
        for (int s = 0; s < 8; s++) {
            u32 pa[4], pl[4];
            split_pack2(sc[2*s    ][0], sc[2*s    ][1], pa[0], pl[0]);
            split_pack2(sc[2*s    ][2], sc[2*s    ][3], pa[1], pl[1]);
            split_pack2(sc[2*s + 1][0], sc[2*s + 1][1], pa[2], pl[2]);
            split_pack2(sc[2*s + 1][2], sc[2*s + 1][3], pa[3], pl[3]);
#pragma unroll
            for (int ntp = 0; ntp < 4; ntp++) {
                int vrow = s * 16 + i8 + ((sel & 1) << 3);
                u32 voff = (u32)(vrow * 128) + ((u32)(((ntp * 2 + (sel >> 1)) ^ i8)) << 4);
                u32 vhr[4], vlr[4];
                ldsm_x4_t(vhr, st + 32768 + voff);
                ldsm_x4_t(vlr, st + 49152 + voff);
                mma16816(oacc[2*ntp],   pa[0], pa[1], pa[2], pa[3], vhr[0], vhr[1]);
                mma16816(oacc[2*ntp],   pa[0], pa[1], pa[2], pa[3], vlr[0], vlr[1]);
                mma16816(oacc[2*ntp],   pl[0], pl[1], pl[2], pl[3], vhr[0], vhr[1]);
                mma16816(oacc[2*ntp+1], pa[0], pa[1], pa[2], pa[3], vhr[2], vhr[3]);
                mma16816(oacc[2*ntp+1], pa[0], pa[1], pa[2], pa[3], vlr[2], vlr[3]);
                mma16816(oacc[2*ntp+1], pl[0], pl[1], pl[2], pl[3], vhr[2], vhr[3]);
            }
        }
    }

    // ---- finalize ----
    lsum0 += __shfl_xor_sync(0xffffffffu, lsum0, 1);
    lsum0 += __shfl_xor_sync(0xffffffffu, lsum0, 2);
    lsum1 += __shfl_xor_sync(0xffffffffu, lsum1, 1);
    lsum1 += __shfl_xor_sync(0xffffffffu, lsum1, 2);
    float il0 = 1.0f / lsum0;
    float il1 = 1.0f / lsum1;
    if (tg == 0) {
        invl[(size_t)bh * SS + rr0    ] = il0;
        invl[(size_t)bh * SS + rr0 + 8] = il1;
    }
    int grow0 = b * SS + rr0;
    int grow1 = grow0 + 8;
    int hcol  = (bh & 15) * DKK;
#pragma unroll
    for (int nt = 0; nt < 8; nt++) {
        int c = hcol + nt * 8 + tg * 2;
        float v00 = oacc[nt][0] * il0, v01 = oacc[nt][1] * il0;
        float v10 = oacc[nt][2] * il1, v11 = oacc[nt][3] * il1;
        bf16 h00, l00, h01, l01, h10, l10, h11, l11;
        f2bf_split(v00, h00, l00); f2bf_split(v01, h01, l01);
        f2bf_split(v10, h10, l10); f2bf_split(v11, h11, l11);
        *(u32*)&o_hi[(size_t)grow0 * DD + c] = bf2_pack(h00, h01);
        *(u32*)&o_lo[(size_t)grow0 * DD + c] = bf2_pack(l00, l01);
        *(u32*)&o_hi[(size_t)grow1 * DD + c] = bf2_pack(h10, h11);
        *(u32*)&o_lo[(size_t)grow1 * DD + c] = bf2_pack(l10, l11);
    }
}

// ---------------------------------------------------------------------------
// p rescale: p *= inv_l[row]
// ---------------------------------------------------------------------------
__global__ void __launch_bounds__(256) pscale_kernel(float* __restrict__ p,
                                                     const float* __restrict__ invl)
{
    size_t idx = (size_t)blockIdx.x * 256 + threadIdx.x;
    float il = __ldg(invl + (idx >> 9));
    float4* p4 = (float4*)p;
    float4 v = p4[idx];
    v.x *= il; v.y *= il; v.z *= il; v.w *= il;
    p4[idx] = v;
}

// ---------------------------------------------------------------------------
// Launch
// ---------------------------------------------------------------------------
extern "C" void kernel_launch(void* const* d_in, const int* in_sizes, int n_in,
                              void* d_out, int out_size)
{
    const float* q    = (const float*)d_in[0];
    const float* k    = (const float*)d_in[1];
    const float* v    = (const float*)d_in[2];
    const unsigned char* mraw = (const unsigned char*)d_in[3];
    const float* bias = (const float*)d_in[4];
    const float* Wq   = (const float*)d_in[5];
    const float* bq   = (const float*)d_in[6];
    const float* Wk   = (const float*)d_in[7];
    const float* bk   = (const float*)d_in[8];
    const float* Wv   = (const float*)d_in[9];
    const float* bv   = (const float*)d_in[10];
    const float* Wo   = (const float*)d_in[11];
    const float* bo   = (const float*)d_in[12];

    float* out = (float*)d_out;
    float* p_out = ((size_t)out_size >= OUT_ELEMS + P_ELEMS) ? out + OUT_ELEMS : nullptr;

    bf16 *aq_hi, *aq_lo, *ak_hi, *ak_lo, *av_hi, *av_lo;
    bf16 *wT_hi, *wT_lo;
    bf16 *qh_hi, *qh_lo, *kh_hi, *kh_lo, *vh_hi, *vh_lo, *o_hi, *o_lo;
    float *mb, *invl;
    cudaGetSymbolAddress((void**)&aq_hi, g_aq_hi);
    cudaGetSymbolAddress((void**)&aq_lo, g_aq_lo);
    cudaGetSymbolAddress((void**)&ak_hi, g_ak_hi);
    cudaGetSymbolAddress((void**)&ak_lo, g_ak_lo);
    cudaGetSymbolAddress((void**)&av_hi, g_av_hi);
    cudaGetSymbolAddress((void**)&av_lo, g_av_lo);
    cudaGetSymbolAddress((void**)&wT_hi, g_wT_hi);
    cudaGetSymbolAddress((void**)&wT_lo, g_wT_lo);
    cudaGetSymbolAddress((void**)&qh_hi, g_qh_hi);
    cudaGetSymbolAddress((void**)&qh_lo, g_qh_lo);
    cudaGetSymbolAddress((void**)&kh_hi, g_kh_hi);
    cudaGetSymbolAddress((void**)&kh_lo, g_kh_lo);
    cudaGetSymbolAddress((void**)&vh_hi, g_vh_hi);
    cudaGetSymbolAddress((void**)&vh_lo, g_vh_lo);
    cudaGetSymbolAddress((void**)&o_hi,  g_o_hi);
    cudaGetSymbolAddress((void**)&o_lo,  g_o_lo);
    cudaGetSymbolAddress((void**)&mb,    g_mb);
    cudaGetSymbolAddress((void**)&invl,  g_invl);

    static bool attr_set = false;
    if (!attr_set) {
        cudaFuncSetAttribute(attn_kernel,
                             cudaFuncAttributeMaxDynamicSharedMemorySize, ATT_SMEM);
        cudaFuncSetAttribute(tgemm_kernel,
                             cudaFuncAttributeMaxDynamicSharedMemorySize, TG_SMEM);
        attr_set = true;
    }

    mask_kernel<<<1, 1024>>>(mraw, mb);

    // pre-split activations and weights
    split_kernel<<<NROWS*DD/4/256, 256>>>((const float4*)q, (uint2*)aq_hi, (uint2*)aq_lo);
    split_kernel<<<NROWS*DD/4/256, 256>>>((const float4*)k, (uint2*)ak_hi, (uint2*)ak_lo);
    split_kernel<<<NROWS*DD/4/256, 256>>>((const float4*)v, (uint2*)av_hi, (uint2*)av_lo);
    dim3 gt(32, 32);
    splitT_kernel<<<gt, 256>>>(Wq, wT_hi + 0*DD*DD, wT_lo + 0*DD*DD);
    splitT_kernel<<<gt, 256>>>(Wk, wT_hi + 1*DD*DD, wT_lo + 1*DD*DD);
    splitT_kernel<<<gt, 256>>>(Wv, wT_hi + 2*DD*DD, wT_lo + 2*DD*DD);
    splitT_kernel<<<gt, 256>>>(Wo, wT_hi + 3*DD*DD, wT_lo + 3*DD*DD);

    dim3 gp(DD / 128, NROWS / 128);   // (8, 32)
    tgemm_kernel<<<gp, 256, TG_SMEM>>>(aq_hi, aq_lo, wT_hi + 0*DD*DD, wT_lo + 0*DD*DD,
                                       bq, nullptr, qh_hi, qh_lo, 1, 0.125f);
    tgemm_kernel<<<gp, 256, TG_SMEM>>>(ak_hi, ak_lo, wT_hi + 1*DD*DD, wT_lo + 1*DD*DD,
                                       bk, nullptr, kh_hi, kh_lo, 1, 1.0f);
    tgemm_kernel<<<gp, 256, TG_SMEM>>>(av_hi, av_lo, wT_hi + 2*DD*DD, wT_lo + 2*DD*DD,
                                       bv, nullptr, vh_hi, vh_lo, 1, 1.0f);

    dim3 ga(SS / 128, BB * HH);       // (16, 32)
    attn_kernel<<<ga, 256, ATT_SMEM>>>(qh_hi, qh_lo, kh_hi, kh_lo, vh_hi, vh_lo,
                                       bias, mb, p_out, invl, o_hi, o_lo);

    if (p_out) {
        pscale_kernel<<<(unsigned)(P_ELEMS / 4 / 256), 256>>>(p_out, invl);
    }

    tgemm_kernel<<<gp, 256, TG_SMEM>>>(o_hi, o_lo, wT_hi + 3*DD*DD, wT_lo + 3*DD*DD,
                                       bo, out, nullptr, nullptr, 0, 1.0f);
}